// round 12
// baseline (speedup 1.0000x reference)
#include <cuda_runtime.h>
#include <cuda_fp16.h>
#include <cstdint>

#define BB 64
#define TT 256
#define ET 1024
#define UDIM 512
#define VV 46
#define N4 2048
#define KDIM 1024
#define KSPLIT 4
#define PADK2 72
#define NBLK 256
#define SMBYTES 36864

// ---------------- device-global state / scratch (allocation-free) ----------------
__device__ __align__(16) __half g_M1t[(size_t)N4 * KDIM];  // [n][k] fp16: k<512 -> W1[k]+U1[k]; else W1[k+1]
__device__ __align__(16) __half g_M2t[(size_t)N4 * KDIM];  // [n][k] fp16: k<512 -> W2[k]; else U2[k-512]
__device__ __align__(16) float g_r1[N4];                   // W1 row 512 (y_t rank-1 term)
__device__ __align__(16) float g_WdT[VV * KDIM];           // Wd transposed [v][k]
__device__ __align__(16) __half g_hh[(size_t)BB * ET * UDIM];  // fp16 encoder h
__device__ __align__(16) __half g_h1h[BB * UDIM];
__device__ __align__(16) __half g_ctxh[BB * UDIM];
__device__ __align__(16) __half g_h2h[BB * UDIM];
__device__ __align__(16) float g_c1[2 * BB * UDIM];        // double-buffered by t parity
__device__ __align__(16) float g_c2[BB * UDIM];
__device__ __align__(16) float g_ctx[BB * UDIM];
__device__ __align__(16) float g_z1p[KSPLIT * BB * N4];
__device__ __align__(16) float g_z2p[KSPLIT * BB * N4];
// attention partials (4 frame-slices per row) + completion counters
__device__ __align__(16) float g_accp[BB * 4 * UDIM];
__device__ float g_mp[BB * 4];
__device__ float g_sp[BB * 4];
__device__ int g_cnt[BB];
__device__ int g_bar;                                      // monotonic global barrier counter

__device__ __forceinline__ float sigf(float x) { return 1.f / (1.f + __expf(-x)); }

__device__ __forceinline__ void cpa16(void* smem, const void* g) {
    unsigned s = (unsigned)__cvta_generic_to_shared(smem);
    asm volatile("cp.async.cg.shared.global [%0], [%1], 16;" :: "r"(s), "l"(g));
}
__device__ __forceinline__ void cpcommit() { asm volatile("cp.async.commit_group;"); }
template <int N> __device__ __forceinline__ void cpwait() {
    asm volatile("cp.async.wait_group %0;" :: "n"(N));
}

// global phase barrier: every block calls with the same monotonically increasing target
__device__ __forceinline__ void gbar(int target) {
    __threadfence();                        // each thread's global writes visible
    __syncthreads();                        // all threads of block fenced
    if (threadIdx.x == 0) {
        atomicAdd(&g_bar, 1);
        volatile int* vb = &g_bar;          // volatile -> L1-bypassing poll, not hoistable
        while (*vb < target) {}
    }
    __syncthreads();
}

// ---------------- prologue ----------------
__global__ void prologue_kernel(const float* __restrict__ W1, const float* __restrict__ U1,
                                const float* __restrict__ W2, const float* __restrict__ U2,
                                const float* __restrict__ Wd, const float* __restrict__ h) {
    int stride = gridDim.x * blockDim.x;
    int t0 = blockIdx.x * blockDim.x + threadIdx.x;
    for (size_t idx = t0; idx < (size_t)N4 * KDIM; idx += stride) {
        int n = idx >> 10;
        int k = idx & (KDIM - 1);
        float m1 = (k < UDIM) ? (W1[(size_t)k * N4 + n] + U1[(size_t)k * N4 + n])
                              : W1[(size_t)(k + 1) * N4 + n];
        float m2 = (k < UDIM) ? W2[(size_t)k * N4 + n] : U2[(size_t)(k - UDIM) * N4 + n];
        g_M1t[idx] = __float2half_rn(m1);
        g_M2t[idx] = __float2half_rn(m2);
    }
    for (int j = t0; j < N4; j += stride) g_r1[j] = W1[UDIM * N4 + j];
    for (int idx = t0; idx < VV * KDIM; idx += stride) {
        int v = idx / KDIM, k = idx % KDIM;
        g_WdT[idx] = Wd[k * VV + v];
    }
    for (size_t idx = t0; idx < (size_t)BB * ET * UDIM; idx += stride)
        g_hh[idx] = __float2half_rn(h[idx]);
    for (int i = t0; i < BB * UDIM; i += stride) {
        g_c1[i] = 0.f; g_c1[BB * UDIM + i] = 0.f;
        g_c2[i] = 0.f; g_ctx[i] = 0.f;
        g_h1h[i] = __float2half_rn(0.f);
        g_ctxh[i] = __float2half_rn(0.f);
        g_h2h[i] = __float2half_rn(0.f);
    }
    for (int i = t0; i < BB; i += stride) g_cnt[i] = 0;
    if (t0 == 0) g_bar = 0;
}

// ---------------- fp16 tensor-core split-K GEMM, depth-2 cp.async pipeline ----------------
// C[64 x 2048] += A[64 x 1024]fp16 @ B[1024 x 2048]fp16, B stored [n][k].
// id: jt = id&31 (N-tile of 64), kc = id>>5 (K-chunk of 256 = 4 stages of 64).
__device__ __forceinline__ void gemm_issue(int buf, int stage, const __half* __restrict__ Asrc,
                                           int koff0, const __half* __restrict__ Bw,
                                           int jbase, int kcbase, __half* As, __half* Bs, int tid) {
    int kA = koff0 + stage * 64;
    int kB = kcbase + stage * 64;
    __half* Ab = As + buf * (64 * PADK2);
    __half* Bb = Bs + buf * (64 * PADK2);
#pragma unroll
    for (int q = 0; q < 2; ++q) {
        int chunk = tid + q * 256;         // 0..511
        int r = chunk >> 3;                // 0..63
        int c8 = (chunk & 7) * 8;          // 0..56
        cpa16(&Ab[r * PADK2 + c8], Asrc + (size_t)r * UDIM + kA + c8);
        cpa16(&Bb[r * PADK2 + c8], Bw + (size_t)(jbase + r) * KDIM + kB + c8);
    }
    cpcommit();
}

__device__ __forceinline__ void gemm_body(int id, const __half* __restrict__ A0,
                                          const __half* __restrict__ A1,
                                          const __half* __restrict__ Bw,
                                          float* __restrict__ zp, char* sm) {
    int jt = id & 31;
    int kc = id >> 5;
    int jbase = jt * 64;
    int kcbase = kc * 256;
    const __half* Asrc = (kc < 2) ? A0 : A1;
    int koff0 = (kc & 1) * 256;

    __half* As = (__half*)sm;                      // 2 x 64 x PADK2
    __half* Bs = As + 2 * 64 * PADK2;              // 2 x 64 x PADK2

    int tid = threadIdx.x;
    int w = tid >> 5, lane = tid & 31;
    int wr = w >> 2, wc = w & 3;           // warp grid 2 x 4
    int m_base = wr * 32, n_base = wc * 16;
    int g = lane >> 2, tg = lane & 3;

    float c[2][2][4];
#pragma unroll
    for (int mt = 0; mt < 2; ++mt)
#pragma unroll
        for (int nt = 0; nt < 2; ++nt)
#pragma unroll
            for (int q = 0; q < 4; ++q) c[mt][nt][q] = 0.f;

    gemm_issue(0, 0, Asrc, koff0, Bw, jbase, kcbase, As, Bs, tid);
    gemm_issue(1, 1, Asrc, koff0, Bw, jbase, kcbase, As, Bs, tid);

    for (int s = 0; s < 4; ++s) {
        if (s < 3) cpwait<1>(); else cpwait<0>();
        __syncthreads();
        int bf = s & 1;
        const __half* Ab = As + bf * (64 * PADK2);
        const __half* Bb = Bs + bf * (64 * PADK2);
#pragma unroll
        for (int ks = 0; ks < 4; ++ks) {
            unsigned a[2][4], bfr[2][2];
#pragma unroll
            for (int mt = 0; mt < 2; ++mt) {
                int row = m_base + mt * 16 + g;
                const __half* base0 = &Ab[row * PADK2 + ks * 16 + tg * 2];
                a[mt][0] = *(const unsigned*)base0;
                a[mt][1] = *(const unsigned*)(base0 + 8 * PADK2);
                a[mt][2] = *(const unsigned*)(base0 + 8);
                a[mt][3] = *(const unsigned*)(base0 + 8 * PADK2 + 8);
            }
#pragma unroll
            for (int nt = 0; nt < 2; ++nt) {
                int col = n_base + nt * 8 + g;
                const __half* base0 = &Bb[col * PADK2 + ks * 16 + tg * 2];
                bfr[nt][0] = *(const unsigned*)base0;
                bfr[nt][1] = *(const unsigned*)(base0 + 8);
            }
#pragma unroll
            for (int mt = 0; mt < 2; ++mt)
#pragma unroll
                for (int nt = 0; nt < 2; ++nt) {
                    asm volatile(
                        "mma.sync.aligned.m16n8k16.row.col.f32.f16.f16.f32 "
                        "{%0,%1,%2,%3}, {%4,%5,%6,%7}, {%8,%9}, {%0,%1,%2,%3};"
                        : "+f"(c[mt][nt][0]), "+f"(c[mt][nt][1]),
                          "+f"(c[mt][nt][2]), "+f"(c[mt][nt][3])
                        : "r"(a[mt][0]), "r"(a[mt][1]), "r"(a[mt][2]), "r"(a[mt][3]),
                          "r"(bfr[nt][0]), "r"(bfr[nt][1]));
                }
        }
        if (s + 2 < 4) {
            __syncthreads();               // all warps done reading buf before refill
            gemm_issue(bf, s + 2, Asrc, koff0, Bw, jbase, kcbase, As, Bs, tid);
        }
    }
    __syncthreads();                       // protect smem reuse by next phase

    float* zb = zp + (size_t)kc * BB * N4;
#pragma unroll
    for (int mt = 0; mt < 2; ++mt)
#pragma unroll
        for (int nt = 0; nt < 2; ++nt) {
            int row0 = m_base + mt * 16 + g;
            int col0 = jbase + n_base + nt * 8 + tg * 2;
            float2 lo = make_float2(c[mt][nt][0], c[mt][nt][1]);
            float2 hi = make_float2(c[mt][nt][2], c[mt][nt][3]);
            *(float2*)(zb + (size_t)row0 * N4 + col0) = lo;
            *(float2*)(zb + (size_t)(row0 + 8) * N4 + col0) = hi;
        }
}

// ---------------- LSTM2 gate finish + logits + output softmax for step tprev ----------------
__device__ __forceinline__ void dec_body(char* sm, int b, int tprev, const float* __restrict__ b2,
                                         const float* __restrict__ bd, float* __restrict__ out) {
    float* xcat = (float*)sm;              // 2*UDIM floats
    float* lg = (float*)(sm + 4096);       // VV floats
    int tid = threadIdx.x;
#pragma unroll
    for (int r = 0; r < 2; ++r) {
        int u = tid + r * 256;
        float z[4];
#pragma unroll
        for (int g = 0; g < 4; ++g) {
            int idx = g * UDIM + u;
            float v = b2[idx];
#pragma unroll
            for (int kc = 0; kc < KSPLIT; ++kc) v += __ldcg(&g_z2p[(size_t)(kc * BB + b) * N4 + idx]);
            z[g] = v;
        }
        float co = g_c2[b * UDIM + u];     // block-private across iterations (same block id)
        float cn = sigf(z[1]) * co + sigf(z[0]) * tanhf(z[2]);
        float hn = sigf(z[3]) * tanhf(cn);
        g_c2[b * UDIM + u] = cn;
        g_h2h[b * UDIM + u] = __float2half_rn(hn);
        xcat[u] = hn;
        xcat[UDIM + u] = __ldcg(&g_ctx[b * UDIM + u]);
    }
    __syncthreads();
    int lane = tid & 31, w = tid >> 5;
    for (int v = w; v < VV; v += 8) {
        float p = 0.f;
        const float* wr = g_WdT + v * KDIM;
        for (int k = lane; k < KDIM; k += 32) p += xcat[k] * wr[k];
#pragma unroll
        for (int off = 16; off; off >>= 1) p += __shfl_xor_sync(0xffffffffu, p, off);
        if (lane == 0) lg[v] = p + bd[v];
    }
    __syncthreads();
    if (tid == 0) {
        float mx = lg[0];
        for (int v = 1; v < VV; ++v) mx = fmaxf(mx, lg[v]);
        float s = 0.f;
        for (int v = 0; v < VV; ++v) { float e = __expf(lg[v] - mx); lg[v] = e; s += e; }
        float inv = 1.f / s;
        for (int v = 0; v < VV; ++v) lg[v] *= inv;
    }
    __syncthreads();
    if (tid < VV) out[((size_t)b * TT + tprev) * VV + tid] = lg[tid];
    __syncthreads();                       // protect smem reuse by next phase
}

// ---------------- attention task: LSTM1 gates + slice online-softmax + last-block combine ----
__device__ __forceinline__ void attn_task(char* sm, const float* __restrict__ yv,
                                          const float* __restrict__ b1, int t, int bid) {
    int p = bid & 3;
    int b = bid >> 2;
    int tid = threadIdx.x;
    int lane = tid & 31, w = tid >> 5;
    float* h1s = (float*)sm;                               // 512 f
    float (*reds)[UDIM] = (float(*)[UDIM])(sm + 2048);     // 8 x 512 f
    float* mwarp = (float*)(sm + 2048 + 16384);            // 8 f
    float* swarp = mwarp + 8;                              // 8 f
    int* is_last_p = (int*)(swarp + 8);

    int par = t & 1;
    const float* c1r = g_c1 + par * BB * UDIM;
    float* c1w = g_c1 + (1 - par) * BB * UDIM;

    float yb = yv[b * TT + t];
#pragma unroll
    for (int r = 0; r < 2; ++r) {
        int u = tid + r * 256;
        float z[4];
#pragma unroll
        for (int g = 0; g < 4; ++g) {
            int idx = g * UDIM + u;
            float vvv = b1[idx] + yb * g_r1[idx];
#pragma unroll
            for (int kc = 0; kc < KSPLIT; ++kc) vvv += __ldcg(&g_z1p[(size_t)(kc * BB + b) * N4 + idx]);
            z[g] = vvv;
        }
        float co = __ldcg(&c1r[b * UDIM + u]);
        float cn = sigf(z[1]) * co + sigf(z[0]) * tanhf(z[2]);
        float hn = sigf(z[3]) * tanhf(cn);
        if (p == 0) {
            c1w[b * UDIM + u] = cn;
            g_h1h[b * UDIM + u] = __float2half_rn(hn);
        }
        h1s[u] = hn;
    }
    __syncthreads();

    float hr[16];
#pragma unroll
    for (int i = 0; i < 4; ++i) *(float4*)&hr[i * 4] = *(const float4*)&h1s[lane * 16 + i * 4];

    float acc[16];
#pragma unroll
    for (int j = 0; j < 16; ++j) acc[j] = 0.f;
    float m = -1e30f, sw = 0.f;
    const __half* hb = g_hh + (size_t)b * ET * UDIM;

    for (int tile = 0; tile < 8; ++tile) {
        int f0 = p * 256 + tile * 32 + w * 4;
        float v[4][16];
        float sc[4];
#pragma unroll
        for (int fi = 0; fi < 4; ++fi) {
            const __half* hf = hb + (size_t)(f0 + fi) * UDIM + lane * 16;
            uint4 p0 = *(const uint4*)hf;
            uint4 p1 = *(const uint4*)(hf + 8);
            const unsigned pk[8] = {p0.x, p0.y, p0.z, p0.w, p1.x, p1.y, p1.z, p1.w};
#pragma unroll
            for (int q = 0; q < 8; ++q) {
                float2 f2 = __half22float2(*(const __half2*)&pk[q]);
                v[fi][q * 2] = f2.x;
                v[fi][q * 2 + 1] = f2.y;
            }
            float s = 0.f;
#pragma unroll
            for (int j = 0; j < 16; ++j) s += hr[j] * v[fi][j];
#pragma unroll
            for (int off = 16; off; off >>= 1) s += __shfl_xor_sync(0xffffffffu, s, off);
            sc[fi] = s;
        }
        float tv = fmaxf(fmaxf(sc[0], sc[1]), fmaxf(sc[2], sc[3]));
        float mn = fmaxf(m, tv);
        float scale = __expf(m - mn);
        m = mn;
        float p0 = __expf(sc[0] - mn), p1 = __expf(sc[1] - mn);
        float p2 = __expf(sc[2] - mn), p3 = __expf(sc[3] - mn);
        sw = sw * scale + (p0 + p1 + p2 + p3);
#pragma unroll
        for (int j = 0; j < 16; ++j)
            acc[j] = acc[j] * scale + p0 * v[0][j] + p1 * v[1][j] + p2 * v[2][j] + p3 * v[3][j];
    }

#pragma unroll
    for (int i = 0; i < 4; ++i) *(float4*)&reds[w][lane * 16 + i * 4] = *(float4*)&acc[i * 4];
    if (lane == 0) { mwarp[w] = m; swarp[w] = sw; }
    __syncthreads();

    // block-level partial over this block's 8 warps
    float gm = mwarp[0];
#pragma unroll
    for (int ww = 1; ww < 8; ++ww) gm = fmaxf(gm, mwarp[ww]);
    float wsc[8];
    float sb = 0.f;
#pragma unroll
    for (int ww = 0; ww < 8; ++ww) { wsc[ww] = __expf(mwarp[ww] - gm); sb += swarp[ww] * wsc[ww]; }
    float* accp = g_accp + (size_t)(b * 4 + p) * UDIM;
#pragma unroll
    for (int r = 0; r < 2; ++r) {
        int d = tid + r * 256;
        float a = 0.f;
#pragma unroll
        for (int ww = 0; ww < 8; ++ww) a += reds[ww][d] * wsc[ww];
        accp[d] = a;
    }
    if (tid == 0) { g_mp[b * 4 + p] = gm; g_sp[b * 4 + p] = sb; }
    __threadfence();                        // all threads fence their partial writes
    __syncthreads();
    if (tid == 0) {
        int old = atomicAdd(&g_cnt[b], 1);
        *is_last_p = (old == 3);
    }
    __syncthreads();
    if (*is_last_p) {
        if (tid == 0) g_cnt[b] = 0;
        float mp4[4], sp4[4];
#pragma unroll
        for (int q = 0; q < 4; ++q) { mp4[q] = __ldcg(&g_mp[b * 4 + q]); sp4[q] = __ldcg(&g_sp[b * 4 + q]); }
        float gm4 = fmaxf(fmaxf(mp4[0], mp4[1]), fmaxf(mp4[2], mp4[3]));
        float wsc4[4];
        float stot = 0.f;
#pragma unroll
        for (int q = 0; q < 4; ++q) { wsc4[q] = __expf(mp4[q] - gm4); stot += sp4[q] * wsc4[q]; }
        float inv = 1.f / stot;
#pragma unroll
        for (int r = 0; r < 2; ++r) {
            int d = tid + r * 256;
            float a = 0.f;
#pragma unroll
            for (int q = 0; q < 4; ++q) a += __ldcg(&g_accp[(size_t)(b * 4 + q) * UDIM + d]) * wsc4[q];
            float cv = a * inv;
            g_ctx[b * UDIM + d] = cv;
            g_ctxh[b * UDIM + d] = __float2half_rn(cv);
        }
    }
    __syncthreads();                        // protect smem reuse by next phase
}

// ---------------- single persistent kernel: whole T=256 recurrence ----------------
__global__ void __launch_bounds__(256, 2) fused_kernel(const float* __restrict__ yv,
                                                       const float* __restrict__ b1,
                                                       const float* __restrict__ b2,
                                                       const float* __restrict__ bd,
                                                       float* __restrict__ out) {
    __shared__ __align__(16) char sm[SMBYTES];
    int bid = blockIdx.x;
    int ep = 0;
    for (int t = 0; t < TT; ++t) {
        // Phase A: z1 GEMM (128 tiles) || LSTM2/logits for t-1 (64 blocks)
        if (bid < 128) gemm_body(bid, g_h1h, g_ctxh, g_M1t, g_z1p, sm);
        else if (bid < 192 && t > 0) dec_body(sm, bid - 128, t - 1, b2, bd, out);
        gbar(++ep * NBLK);
        // Phase B: attention (256 slice blocks, in-phase combine)
        attn_task(sm, yv, b1, t, bid);
        gbar(++ep * NBLK);
        // Phase C: z2 GEMM (128 tiles)
        if (bid < 128) gemm_body(bid, g_ctxh, g_h2h, g_M2t, g_z2p, sm);
        gbar(++ep * NBLK);
    }
    // epilogue: final LSTM2/logits (same blocks as loop dec -> c2 stays block-private)
    if (bid >= 128 && bid < 192) dec_body(sm, bid - 128, TT - 1, b2, bd, out);
}

// ---------------- launcher (graph-capturable: kernel launches only) ----------------
extern "C" void kernel_launch(void* const* d_in, const int* in_sizes, int n_in,
                              void* d_out, int out_size) {
    (void)in_sizes; (void)n_in; (void)out_size;
    const float* h  = (const float*)d_in[0];
    const float* y  = (const float*)d_in[1];
    const float* W1 = (const float*)d_in[2];
    const float* U1 = (const float*)d_in[3];
    const float* b1 = (const float*)d_in[4];
    const float* W2 = (const float*)d_in[5];
    const float* U2 = (const float*)d_in[6];
    const float* b2 = (const float*)d_in[7];
    const float* Wd = (const float*)d_in[8];
    const float* bd = (const float*)d_in[9];
    float* out = (float*)d_out;

    prologue_kernel<<<1024, 256>>>(W1, U1, W2, U2, Wd, h);
    fused_kernel<<<NBLK, 256>>>(y, b1, b2, bd, out);
}

// round 13
// speedup vs baseline: 1.3487x; 1.3487x over previous
#include <cuda_runtime.h>
#include <cuda_fp16.h>
#include <cstdint>

#define BB 64
#define TT 256
#define ET 1024
#define UDIM 512
#define VV 46
#define N4 2048
#define KDIM 1024
#define KSPLIT 4
#define PADK2 72
#define NBLK 256
#define SMBYTES 36864

// ---------------- device-global state / scratch (allocation-free) ----------------
__device__ __align__(16) __half g_M1t[(size_t)N4 * KDIM];  // [n][k] fp16: k<512 -> W1[k]+U1[k]; else W1[k+1]
__device__ __align__(16) __half g_M2t[(size_t)N4 * KDIM];  // [n][k] fp16: k<512 -> W2[k]; else U2[k-512]
__device__ __align__(16) float g_r1[N4];                   // W1 row 512 (y_t rank-1 term)
__device__ __align__(16) float g_WdT[VV * KDIM];           // Wd transposed [v][k]
__device__ __align__(16) __half g_hh[(size_t)BB * ET * UDIM];  // fp16 encoder h
__device__ __align__(16) __half g_h1h[BB * UDIM];
__device__ __align__(16) __half g_ctxh[BB * UDIM];
__device__ __align__(16) __half g_h2h[BB * UDIM];
__device__ __align__(16) float g_c1[2 * BB * UDIM];        // double-buffered by t parity
__device__ __align__(16) float g_c2[BB * UDIM];
__device__ __align__(16) float g_ctx[2 * BB * UDIM];       // fp32 ctx, parity double-buffered
__device__ __align__(16) float g_z1p[KSPLIT * BB * N4];
__device__ __align__(16) float g_z2p[KSPLIT * BB * N4];
// attention partials (3 frame-slices per row) + completion counters
__device__ __align__(16) float g_accp[BB * 4 * UDIM];
__device__ float g_mp[BB * 4];
__device__ float g_sp[BB * 4];
__device__ int g_cnt[BB];
__device__ int g_bar;                                      // monotonic global barrier counter

__device__ __forceinline__ float sigf(float x) { return 1.f / (1.f + __expf(-x)); }

__device__ __forceinline__ void cpa16(void* smem, const void* g) {
    unsigned s = (unsigned)__cvta_generic_to_shared(smem);
    asm volatile("cp.async.cg.shared.global [%0], [%1], 16;" :: "r"(s), "l"(g));
}
__device__ __forceinline__ void cpcommit() { asm volatile("cp.async.commit_group;"); }
template <int N> __device__ __forceinline__ void cpwait() {
    asm volatile("cp.async.wait_group %0;" :: "n"(N));
}

// global phase barrier: every block calls with the same monotonically increasing target
__device__ __forceinline__ void gbar(int target) {
    __threadfence();
    __syncthreads();
    if (threadIdx.x == 0) {
        atomicAdd(&g_bar, 1);
        volatile int* vb = &g_bar;
        while (*vb < target) {}
    }
    __syncthreads();
}

// ---------------- prologue ----------------
__global__ void prologue_kernel(const float* __restrict__ W1, const float* __restrict__ U1,
                                const float* __restrict__ W2, const float* __restrict__ U2,
                                const float* __restrict__ Wd, const float* __restrict__ h) {
    int stride = gridDim.x * blockDim.x;
    int t0 = blockIdx.x * blockDim.x + threadIdx.x;
    for (size_t idx = t0; idx < (size_t)N4 * KDIM; idx += stride) {
        int n = idx >> 10;
        int k = idx & (KDIM - 1);
        float m1 = (k < UDIM) ? (W1[(size_t)k * N4 + n] + U1[(size_t)k * N4 + n])
                              : W1[(size_t)(k + 1) * N4 + n];
        float m2 = (k < UDIM) ? W2[(size_t)k * N4 + n] : U2[(size_t)(k - UDIM) * N4 + n];
        g_M1t[idx] = __float2half_rn(m1);
        g_M2t[idx] = __float2half_rn(m2);
    }
    for (int j = t0; j < N4; j += stride) g_r1[j] = W1[UDIM * N4 + j];
    for (int idx = t0; idx < VV * KDIM; idx += stride) {
        int v = idx / KDIM, k = idx % KDIM;
        g_WdT[idx] = Wd[k * VV + v];
    }
    for (size_t idx = t0; idx < (size_t)BB * ET * UDIM; idx += stride)
        g_hh[idx] = __float2half_rn(h[idx]);
    for (int i = t0; i < BB * UDIM; i += stride) {
        g_c1[i] = 0.f; g_c1[BB * UDIM + i] = 0.f;
        g_c2[i] = 0.f;
        g_ctx[i] = 0.f; g_ctx[BB * UDIM + i] = 0.f;
        g_h1h[i] = __float2half_rn(0.f);
        g_ctxh[i] = __float2half_rn(0.f);
        g_h2h[i] = __float2half_rn(0.f);
    }
    for (int i = t0; i < BB; i += stride) g_cnt[i] = 0;
    if (t0 == 0) g_bar = 0;
}

// ---------------- fp16 tensor-core split-K GEMM, depth-2 cp.async pipeline ----------------
// C[64 x 2048] += A[64 x 1024]fp16 @ B[1024 x 2048]fp16, B stored [n][k].
// id: jt = id&31 (N-tile of 64), kc = id>>5 (K-chunk of 256 = 4 stages of 64).
__device__ __forceinline__ void gemm_issue(int buf, int stage, const __half* __restrict__ Asrc,
                                           int koff0, const __half* __restrict__ Bw,
                                           int jbase, int kcbase, __half* As, __half* Bs, int tid) {
    int kA = koff0 + stage * 64;
    int kB = kcbase + stage * 64;
    __half* Ab = As + buf * (64 * PADK2);
    __half* Bb = Bs + buf * (64 * PADK2);
#pragma unroll
    for (int q = 0; q < 2; ++q) {
        int chunk = tid + q * 256;         // 0..511
        int r = chunk >> 3;                // 0..63
        int c8 = (chunk & 7) * 8;          // 0..56
        cpa16(&Ab[r * PADK2 + c8], Asrc + (size_t)r * UDIM + kA + c8);
        cpa16(&Bb[r * PADK2 + c8], Bw + (size_t)(jbase + r) * KDIM + kB + c8);
    }
    cpcommit();
}

__device__ __forceinline__ void gemm_body(int id, const __half* __restrict__ A0,
                                          const __half* __restrict__ A1,
                                          const __half* __restrict__ Bw,
                                          float* __restrict__ zp, char* sm) {
    int jt = id & 31;
    int kc = id >> 5;
    int jbase = jt * 64;
    int kcbase = kc * 256;
    const __half* Asrc = (kc < 2) ? A0 : A1;
    int koff0 = (kc & 1) * 256;

    __half* As = (__half*)sm;                      // 2 x 64 x PADK2
    __half* Bs = As + 2 * 64 * PADK2;              // 2 x 64 x PADK2

    int tid = threadIdx.x;
    int w = tid >> 5, lane = tid & 31;
    int wr = w >> 2, wc = w & 3;           // warp grid 2 x 4
    int m_base = wr * 32, n_base = wc * 16;
    int g = lane >> 2, tg = lane & 3;

    float c[2][2][4];
#pragma unroll
    for (int mt = 0; mt < 2; ++mt)
#pragma unroll
        for (int nt = 0; nt < 2; ++nt)
#pragma unroll
            for (int q = 0; q < 4; ++q) c[mt][nt][q] = 0.f;

    gemm_issue(0, 0, Asrc, koff0, Bw, jbase, kcbase, As, Bs, tid);
    gemm_issue(1, 1, Asrc, koff0, Bw, jbase, kcbase, As, Bs, tid);

    for (int s = 0; s < 4; ++s) {
        if (s < 3) cpwait<1>(); else cpwait<0>();
        __syncthreads();
        int bf = s & 1;
        const __half* Ab = As + bf * (64 * PADK2);
        const __half* Bb = Bs + bf * (64 * PADK2);
#pragma unroll
        for (int ks = 0; ks < 4; ++ks) {
            unsigned a[2][4], bfr[2][2];
#pragma unroll
            for (int mt = 0; mt < 2; ++mt) {
                int row = m_base + mt * 16 + g;
                const __half* base0 = &Ab[row * PADK2 + ks * 16 + tg * 2];
                a[mt][0] = *(const unsigned*)base0;
                a[mt][1] = *(const unsigned*)(base0 + 8 * PADK2);
                a[mt][2] = *(const unsigned*)(base0 + 8);
                a[mt][3] = *(const unsigned*)(base0 + 8 * PADK2 + 8);
            }
#pragma unroll
            for (int nt = 0; nt < 2; ++nt) {
                int col = n_base + nt * 8 + g;
                const __half* base0 = &Bb[col * PADK2 + ks * 16 + tg * 2];
                bfr[nt][0] = *(const unsigned*)base0;
                bfr[nt][1] = *(const unsigned*)(base0 + 8);
            }
#pragma unroll
            for (int mt = 0; mt < 2; ++mt)
#pragma unroll
                for (int nt = 0; nt < 2; ++nt) {
                    asm volatile(
                        "mma.sync.aligned.m16n8k16.row.col.f32.f16.f16.f32 "
                        "{%0,%1,%2,%3}, {%4,%5,%6,%7}, {%8,%9}, {%0,%1,%2,%3};"
                        : "+f"(c[mt][nt][0]), "+f"(c[mt][nt][1]),
                          "+f"(c[mt][nt][2]), "+f"(c[mt][nt][3])
                        : "r"(a[mt][0]), "r"(a[mt][1]), "r"(a[mt][2]), "r"(a[mt][3]),
                          "r"(bfr[nt][0]), "r"(bfr[nt][1]));
                }
        }
        if (s + 2 < 4) {
            __syncthreads();               // all warps done reading buf before refill
            gemm_issue(bf, s + 2, Asrc, koff0, Bw, jbase, kcbase, As, Bs, tid);
        }
    }
    __syncthreads();                       // protect smem reuse by next phase

    float* zb = zp + (size_t)kc * BB * N4;
#pragma unroll
    for (int mt = 0; mt < 2; ++mt)
#pragma unroll
        for (int nt = 0; nt < 2; ++nt) {
            int row0 = m_base + mt * 16 + g;
            int col0 = jbase + n_base + nt * 8 + tg * 2;
            float2 lo = make_float2(c[mt][nt][0], c[mt][nt][1]);
            float2 hi = make_float2(c[mt][nt][2], c[mt][nt][3]);
            *(float2*)(zb + (size_t)row0 * N4 + col0) = lo;
            *(float2*)(zb + (size_t)(row0 + 8) * N4 + col0) = hi;
        }
}

// ---------------- LSTM2 gate finish + logits + output softmax for step tprev ----------------
// cpar selects which fp32 ctx parity buffer tprev's ctx lives in.
__device__ __forceinline__ void dec_body(char* sm, int b, int tprev, int cpar,
                                         const float* __restrict__ b2,
                                         const float* __restrict__ bd, float* __restrict__ out) {
    float* xcat = (float*)sm;              // 2*UDIM floats
    float* lg = (float*)(sm + 4096);       // VV floats
    int tid = threadIdx.x;
    const float* ctxr = g_ctx + (size_t)cpar * BB * UDIM;
#pragma unroll
    for (int r = 0; r < 2; ++r) {
        int u = tid + r * 256;
        float z[4];
#pragma unroll
        for (int g = 0; g < 4; ++g) {
            int idx = g * UDIM + u;
            float v = b2[idx];
#pragma unroll
            for (int kc = 0; kc < KSPLIT; ++kc) v += __ldcg(&g_z2p[(size_t)(kc * BB + b) * N4 + idx]);
            z[g] = v;
        }
        float co = g_c2[b * UDIM + u];     // block-private (same block id each step)
        float cn = sigf(z[1]) * co + sigf(z[0]) * tanhf(z[2]);
        float hn = sigf(z[3]) * tanhf(cn);
        g_c2[b * UDIM + u] = cn;
        g_h2h[b * UDIM + u] = __float2half_rn(hn);
        xcat[u] = hn;
        xcat[UDIM + u] = __ldcg(&ctxr[b * UDIM + u]);
    }
    __syncthreads();
    int lane = tid & 31, w = tid >> 5;
    for (int v = w; v < VV; v += 8) {
        float p = 0.f;
        const float* wr = g_WdT + v * KDIM;
        for (int k = lane; k < KDIM; k += 32) p += xcat[k] * wr[k];
#pragma unroll
        for (int off = 16; off; off >>= 1) p += __shfl_xor_sync(0xffffffffu, p, off);
        if (lane == 0) lg[v] = p + bd[v];
    }
    __syncthreads();
    if (tid == 0) {
        float mx = lg[0];
        for (int v = 1; v < VV; ++v) mx = fmaxf(mx, lg[v]);
        float s = 0.f;
        for (int v = 0; v < VV; ++v) { float e = __expf(lg[v] - mx); lg[v] = e; s += e; }
        float inv = 1.f / s;
        for (int v = 0; v < VV; ++v) lg[v] *= inv;
    }
    __syncthreads();
    if (tid < VV) out[((size_t)b * TT + tprev) * VV + tid] = lg[tid];
    __syncthreads();                       // protect smem reuse by next phase
}

// ---------------- attention task: LSTM1 gates + 3-slice online-softmax + last-block combine ----
// blocks 0..191: b = bid & 63, p = bid >> 6 in {0,1,2}; slices = 11/11/10 tiles of 32 frames.
__device__ __forceinline__ void attn_task(char* sm, const float* __restrict__ yv,
                                          const float* __restrict__ b1, int t, int bid) {
    int b = bid & 63;
    int p = bid >> 6;
    int tid = threadIdx.x;
    int lane = tid & 31, w = tid >> 5;
    float* h1s = (float*)sm;                               // 512 f
    float (*reds)[UDIM] = (float(*)[UDIM])(sm + 2048);     // 8 x 512 f
    float* mwarp = (float*)(sm + 2048 + 16384);            // 8 f
    float* swarp = mwarp + 8;                              // 8 f
    int* is_last_p = (int*)(swarp + 8);

    int par = t & 1;
    const float* c1r = g_c1 + par * BB * UDIM;
    float* c1w = g_c1 + (1 - par) * BB * UDIM;
    float* ctxw = g_ctx + (size_t)par * BB * UDIM;         // ctx(t) -> parity t&1

    float yb = yv[b * TT + t];
#pragma unroll
    for (int r = 0; r < 2; ++r) {
        int u = tid + r * 256;
        float z[4];
#pragma unroll
        for (int g = 0; g < 4; ++g) {
            int idx = g * UDIM + u;
            float vvv = b1[idx] + yb * g_r1[idx];
#pragma unroll
            for (int kc = 0; kc < KSPLIT; ++kc) vvv += __ldcg(&g_z1p[(size_t)(kc * BB + b) * N4 + idx]);
            z[g] = vvv;
        }
        float co = __ldcg(&c1r[b * UDIM + u]);
        float cn = sigf(z[1]) * co + sigf(z[0]) * tanhf(z[2]);
        float hn = sigf(z[3]) * tanhf(cn);
        if (p == 0) {
            c1w[b * UDIM + u] = cn;
            g_h1h[b * UDIM + u] = __float2half_rn(hn);
        }
        h1s[u] = hn;
    }
    __syncthreads();

    float hr[16];
#pragma unroll
    for (int i = 0; i < 4; ++i) *(float4*)&hr[i * 4] = *(const float4*)&h1s[lane * 16 + i * 4];

    float acc[16];
#pragma unroll
    for (int j = 0; j < 16; ++j) acc[j] = 0.f;
    float m = -1e30f, sw = 0.f;
    const __half* hb = g_hh + (size_t)b * ET * UDIM;

    int tile0 = p * 11;                    // p=0:0, p=1:11, p=2:22
    int ntile = (p < 2) ? 11 : 10;         // 352/352/320 frames
    for (int tile = 0; tile < ntile; ++tile) {
        int f0 = (tile0 + tile) * 32 + w * 4;
        float v[4][16];
        float sc[4];
#pragma unroll
        for (int fi = 0; fi < 4; ++fi) {
            const __half* hf = hb + (size_t)(f0 + fi) * UDIM + lane * 16;
            uint4 p0 = *(const uint4*)hf;
            uint4 p1 = *(const uint4*)(hf + 8);
            const unsigned pk[8] = {p0.x, p0.y, p0.z, p0.w, p1.x, p1.y, p1.z, p1.w};
#pragma unroll
            for (int q = 0; q < 8; ++q) {
                float2 f2 = __half22float2(*(const __half2*)&pk[q]);
                v[fi][q * 2] = f2.x;
                v[fi][q * 2 + 1] = f2.y;
            }
            float s = 0.f;
#pragma unroll
            for (int j = 0; j < 16; ++j) s += hr[j] * v[fi][j];
#pragma unroll
            for (int off = 16; off; off >>= 1) s += __shfl_xor_sync(0xffffffffu, s, off);
            sc[fi] = s;
        }
        float tv = fmaxf(fmaxf(sc[0], sc[1]), fmaxf(sc[2], sc[3]));
        float mn = fmaxf(m, tv);
        float scale = __expf(m - mn);
        m = mn;
        float p0 = __expf(sc[0] - mn), p1 = __expf(sc[1] - mn);
        float p2 = __expf(sc[2] - mn), p3 = __expf(sc[3] - mn);
        sw = sw * scale + (p0 + p1 + p2 + p3);
#pragma unroll
        for (int j = 0; j < 16; ++j)
            acc[j] = acc[j] * scale + p0 * v[0][j] + p1 * v[1][j] + p2 * v[2][j] + p3 * v[3][j];
    }

#pragma unroll
    for (int i = 0; i < 4; ++i) *(float4*)&reds[w][lane * 16 + i * 4] = *(float4*)&acc[i * 4];
    if (lane == 0) { mwarp[w] = m; swarp[w] = sw; }
    __syncthreads();

    // block-level partial over this block's 8 warps
    float gm = mwarp[0];
#pragma unroll
    for (int ww = 1; ww < 8; ++ww) gm = fmaxf(gm, mwarp[ww]);
    float wsc[8];
    float sb = 0.f;
#pragma unroll
    for (int ww = 0; ww < 8; ++ww) { wsc[ww] = __expf(mwarp[ww] - gm); sb += swarp[ww] * wsc[ww]; }
    float* accp = g_accp + (size_t)(b * 4 + p) * UDIM;
#pragma unroll
    for (int r = 0; r < 2; ++r) {
        int d = tid + r * 256;
        float a = 0.f;
#pragma unroll
        for (int ww = 0; ww < 8; ++ww) a += reds[ww][d] * wsc[ww];
        accp[d] = a;
    }
    if (tid == 0) { g_mp[b * 4 + p] = gm; g_sp[b * 4 + p] = sb; }
    __threadfence();
    __syncthreads();
    if (tid == 0) {
        int old = atomicAdd(&g_cnt[b], 1);
        *is_last_p = (old == 2);           // 3 slices
    }
    __syncthreads();
    if (*is_last_p) {
        if (tid == 0) g_cnt[b] = 0;
        float mp3[3], sp3[3];
#pragma unroll
        for (int q = 0; q < 3; ++q) { mp3[q] = __ldcg(&g_mp[b * 4 + q]); sp3[q] = __ldcg(&g_sp[b * 4 + q]); }
        float gm3 = fmaxf(fmaxf(mp3[0], mp3[1]), mp3[2]);
        float wsc3[3];
        float stot = 0.f;
#pragma unroll
        for (int q = 0; q < 3; ++q) { wsc3[q] = __expf(mp3[q] - gm3); stot += sp3[q] * wsc3[q]; }
        float inv = 1.f / stot;
#pragma unroll
        for (int r = 0; r < 2; ++r) {
            int d = tid + r * 256;
            float a = 0.f;
#pragma unroll
            for (int q = 0; q < 3; ++q) a += __ldcg(&g_accp[(size_t)(b * 4 + q) * UDIM + d]) * wsc3[q];
            float cv = a * inv;
            ctxw[b * UDIM + d] = cv;
            g_ctxh[b * UDIM + d] = __float2half_rn(cv);
        }
    }
    __syncthreads();                        // protect smem reuse by next phase
}

// ---------------- single persistent kernel: 2 phases per step ----------------
__global__ void __launch_bounds__(256, 2) fused_kernel(const float* __restrict__ yv,
                                                       const float* __restrict__ b1,
                                                       const float* __restrict__ b2,
                                                       const float* __restrict__ bd,
                                                       float* __restrict__ out) {
    __shared__ __align__(16) char sm[SMBYTES];
    int bid = blockIdx.x;
    int ep = 0;
    // init phase: z1 GEMM for t=0 (h1,ctx are zero)
    if (bid >= 128) gemm_body(bid - 128, g_h1h, g_ctxh, g_M1t, g_z1p, sm);
    gbar(++ep * NBLK);
    for (int t = 0; t < TT; ++t) {
        // Phase X: attention(t) on blocks 0..191  ||  dec(t-1) on blocks 192..255
        if (bid < 192) attn_task(sm, yv, b1, t, bid);
        else if (t > 0) dec_body(sm, bid - 192, t - 1, (t - 1) & 1, b2, bd, out);
        gbar(++ep * NBLK);
        // Phase Y: z2 GEMM(t) on blocks 0..127  ||  z1 GEMM(t+1) on blocks 128..255
        if (bid < 128) gemm_body(bid, g_ctxh, g_h2h, g_M2t, g_z2p, sm);
        else if (t + 1 < TT) gemm_body(bid - 128, g_h1h, g_ctxh, g_M1t, g_z1p, sm);
        gbar(++ep * NBLK);
    }
    // epilogue: final LSTM2/logits (same blocks as loop dec -> c2 stays block-private)
    if (bid >= 192) dec_body(sm, bid - 192, TT - 1, (TT - 1) & 1, b2, bd, out);
}

// ---------------- launcher (graph-capturable: kernel launches only) ----------------
extern "C" void kernel_launch(void* const* d_in, const int* in_sizes, int n_in,
                              void* d_out, int out_size) {
    (void)in_sizes; (void)n_in; (void)out_size;
    const float* h  = (const float*)d_in[0];
    const float* y  = (const float*)d_in[1];
    const float* W1 = (const float*)d_in[2];
    const float* U1 = (const float*)d_in[3];
    const float* b1 = (const float*)d_in[4];
    const float* W2 = (const float*)d_in[5];
    const float* U2 = (const float*)d_in[6];
    const float* b2 = (const float*)d_in[7];
    const float* Wd = (const float*)d_in[8];
    const float* bd = (const float*)d_in[9];
    float* out = (float*)d_out;

    prologue_kernel<<<1024, 256>>>(W1, U1, W2, U2, Wd, h);
    fused_kernel<<<NBLK, 256>>>(y, b1, b2, bd, out);
}

// round 17
// speedup vs baseline: 1.3989x; 1.0372x over previous
#include <cuda_runtime.h>
#include <cuda_fp16.h>
#include <cstdint>

#define BB 64
#define TT 256
#define ET 1024
#define UDIM 512
#define VV 46
#define N4 2048
#define KDIM 1024
#define KSPLIT 4
#define PADK2 72
#define NBLK 256

// dynamic smem: 4 independent GEMM stages, each {A: 64xPADK2 halfs, B: 64xPADK2 halfs}
#define STG_BYTES (2 * 64 * PADK2 * 2)          // 18432
#define SA_OFF(s) ((s) * STG_BYTES)
#define SB_OFF(s) ((s) * STG_BYTES + 64 * PADK2 * 2)
#define SMBYTES_DYN (4 * STG_BYTES)             // 73728

__device__ __align__(16) __half g_M1t[(size_t)N4 * KDIM];
__device__ __align__(16) __half g_M2t[(size_t)N4 * KDIM];
__device__ __align__(16) float g_r1[N4];
__device__ __align__(16) float g_WdT[VV * KDIM];
__device__ __align__(16) __half g_hh[(size_t)BB * ET * UDIM];
__device__ __align__(16) __half g_h1h[BB * UDIM];
__device__ __align__(16) __half g_ctxh[BB * UDIM];
__device__ __align__(16) __half g_h2h[BB * UDIM];
__device__ __align__(16) float g_c1[2 * BB * UDIM];
__device__ __align__(16) float g_c2[BB * UDIM];
__device__ __align__(16) float g_ctx[2 * BB * UDIM];
__device__ __align__(16) float g_z1p[KSPLIT * BB * N4];
__device__ __align__(16) float g_z2p[KSPLIT * BB * N4];
__device__ __align__(16) float g_accp[BB * 4 * UDIM];
__device__ float g_mp[BB * 4];
__device__ float g_sp[BB * 4];
__device__ int g_cnt[BB];
__device__ int g_bar;

__device__ __forceinline__ float sigf(float x) { return 1.f / (1.f + __expf(-x)); }

__device__ __forceinline__ void cpa16(void* smem, const void* g) {
    unsigned s = (unsigned)__cvta_generic_to_shared(smem);
    asm volatile("cp.async.cg.shared.global [%0], [%1], 16;" :: "r"(s), "l"(g));
}
__device__ __forceinline__ void cpcommit() { asm volatile("cp.async.commit_group;"); }
template <int N> __device__ __forceinline__ void cpwait() {
    asm volatile("cp.async.wait_group %0;" :: "n"(N));
}

// global phase barrier
__device__ __forceinline__ void gbar(int target) {
    __threadfence();
    __syncthreads();
    if (threadIdx.x == 0) {
        atomicAdd(&g_bar, 1);
        volatile int* vb = &g_bar;
        while (*vb < target) {}
    }
    __syncthreads();
}

// ---------------- prologue ----------------
__global__ void prologue_kernel(const float* __restrict__ W1, const float* __restrict__ U1,
                                const float* __restrict__ W2, const float* __restrict__ U2,
                                const float* __restrict__ Wd, const float* __restrict__ h) {
    int stride = gridDim.x * blockDim.x;
    int t0 = blockIdx.x * blockDim.x + threadIdx.x;
    for (size_t idx = t0; idx < (size_t)N4 * KDIM; idx += stride) {
        int n = idx >> 10;
        int k = idx & (KDIM - 1);
        float m1 = (k < UDIM) ? (W1[(size_t)k * N4 + n] + U1[(size_t)k * N4 + n])
                              : W1[(size_t)(k + 1) * N4 + n];
        float m2 = (k < UDIM) ? W2[(size_t)k * N4 + n] : U2[(size_t)(k - UDIM) * N4 + n];
        g_M1t[idx] = __float2half_rn(m1);
        g_M2t[idx] = __float2half_rn(m2);
    }
    for (int j = t0; j < N4; j += stride) g_r1[j] = W1[UDIM * N4 + j];
    for (int idx = t0; idx < VV * KDIM; idx += stride) {
        int v = idx / KDIM, k = idx % KDIM;
        g_WdT[idx] = Wd[k * VV + v];
    }
    for (size_t idx = t0; idx < (size_t)BB * ET * UDIM; idx += stride)
        g_hh[idx] = __float2half_rn(h[idx]);
    for (int i = t0; i < BB * UDIM; i += stride) {
        g_c1[i] = 0.f; g_c1[BB * UDIM + i] = 0.f;
        g_c2[i] = 0.f;
        g_ctx[i] = 0.f; g_ctx[BB * UDIM + i] = 0.f;
        g_h1h[i] = __float2half_rn(0.f);
        g_ctxh[i] = __float2half_rn(0.f);
        g_h2h[i] = __float2half_rn(0.f);
    }
    for (int i = t0; i < BB; i += stride) g_cnt[i] = 0;
    if (t0 == 0) g_bar = 0;
}

// ---------------- fp16 HMMA split-K GEMM, full 4-stage prefetch (no buffer reuse) ----------------
// C[64 x 2048] += A[64 x 1024]fp16 @ B[1024 x 2048]fp16, B stored [n][k].
// id: jt = id&31 (N-tile of 64), kc = id>>5 (K-chunk of 256 = 4 stages of 64).
__device__ __forceinline__ void gemm_body(int id, const __half* __restrict__ A0,
                                          const __half* __restrict__ A1,
                                          const __half* __restrict__ Bw,
                                          float* __restrict__ zp, char* sm) {
    int jt = id & 31;
    int kc = id >> 5;
    int jbase = jt * 64;
    int kcbase = kc * 256;
    const __half* Asrc = (kc < 2) ? A0 : A1;
    int koff0 = (kc & 1) * 256;

    int tid = threadIdx.x;
    int w = tid >> 5, lane = tid & 31;
    int wr = w >> 2, wc = w & 3;           // warp grid 2 x 4
    int m_base = wr * 32, n_base = wc * 16;
    int g = lane >> 2, tg = lane & 3;

    float c[2][2][4];
#pragma unroll
    for (int mt = 0; mt < 2; ++mt)
#pragma unroll
        for (int nt = 0; nt < 2; ++nt)
#pragma unroll
            for (int q = 0; q < 4; ++q) c[mt][nt][q] = 0.f;

    // issue ALL 4 stages up front (4 commit groups); distinct buffers -> no refill syncs
#pragma unroll
    for (int s = 0; s < 4; ++s) {
        __half* Ab = (__half*)(sm + SA_OFF(s));
        __half* Bb = (__half*)(sm + SB_OFF(s));
#pragma unroll
        for (int q = 0; q < 2; ++q) {
            int chunk = tid + q * 256;     // 0..511
            int r = chunk >> 3;            // 0..63
            int c8 = (chunk & 7) * 8;      // 0..56
            cpa16(&Ab[r * PADK2 + c8], Asrc + (size_t)r * UDIM + koff0 + s * 64 + c8);
            cpa16(&Bb[r * PADK2 + c8], Bw + (size_t)(jbase + r) * KDIM + kcbase + s * 64 + c8);
        }
        cpcommit();
    }

#pragma unroll
    for (int s = 0; s < 4; ++s) {
        if (s == 0) cpwait<3>(); else if (s == 1) cpwait<2>(); else if (s == 2) cpwait<1>(); else cpwait<0>();
        __syncthreads();
        const __half* Ab = (const __half*)(sm + SA_OFF(s));
        const __half* Bb = (const __half*)(sm + SB_OFF(s));
#pragma unroll
        for (int ks = 0; ks < 4; ++ks) {
            unsigned a[2][4], bfr[2][2];
#pragma unroll
            for (int mt = 0; mt < 2; ++mt) {
                int row = m_base + mt * 16 + g;
                const __half* base0 = &Ab[row * PADK2 + ks * 16 + tg * 2];
                a[mt][0] = *(const unsigned*)base0;
                a[mt][1] = *(const unsigned*)(base0 + 8 * PADK2);
                a[mt][2] = *(const unsigned*)(base0 + 8);
                a[mt][3] = *(const unsigned*)(base0 + 8 * PADK2 + 8);
            }
#pragma unroll
            for (int nt = 0; nt < 2; ++nt) {
                int col = n_base + nt * 8 + g;
                const __half* base0 = &Bb[col * PADK2 + ks * 16 + tg * 2];
                bfr[nt][0] = *(const unsigned*)base0;
                bfr[nt][1] = *(const unsigned*)(base0 + 8);
            }
#pragma unroll
            for (int mt = 0; mt < 2; ++mt)
#pragma unroll
                for (int nt = 0; nt < 2; ++nt) {
                    asm volatile(
                        "mma.sync.aligned.m16n8k16.row.col.f32.f16.f16.f32 "
                        "{%0,%1,%2,%3}, {%4,%5,%6,%7}, {%8,%9}, {%0,%1,%2,%3};"
                        : "+f"(c[mt][nt][0]), "+f"(c[mt][nt][1]),
                          "+f"(c[mt][nt][2]), "+f"(c[mt][nt][3])
                        : "r"(a[mt][0]), "r"(a[mt][1]), "r"(a[mt][2]), "r"(a[mt][3]),
                          "r"(bfr[nt][0]), "r"(bfr[nt][1]));
                }
        }
    }
    __syncthreads();                       // protect smem reuse by next phase

    float* zb = zp + (size_t)kc * BB * N4;
#pragma unroll
    for (int mt = 0; mt < 2; ++mt)
#pragma unroll
        for (int nt = 0; nt < 2; ++nt) {
            int row0 = m_base + mt * 16 + g;
            int col0 = jbase + n_base + nt * 8 + tg * 2;
            float2 lo = make_float2(c[mt][nt][0], c[mt][nt][1]);
            float2 hi = make_float2(c[mt][nt][2], c[mt][nt][3]);
            *(float2*)(zb + (size_t)row0 * N4 + col0) = lo;
            *(float2*)(zb + (size_t)(row0 + 8) * N4 + col0) = hi;
        }
}

// ---------------- LSTM2 gate finish + logits + output softmax for step tprev ----------------
__device__ __forceinline__ void dec_body(char* sm, int b, int tprev, int cpar,
                                         const float* __restrict__ b2,
                                         const float* __restrict__ bd, float* __restrict__ out) {
    float* xcat = (float*)sm;
    float* lg = (float*)(sm + 4096);
    int tid = threadIdx.x;
    const float* ctxr = g_ctx + (size_t)cpar * BB * UDIM;
#pragma unroll
    for (int r = 0; r < 2; ++r) {
        int u = tid + r * 256;
        float z[4];
#pragma unroll
        for (int g = 0; g < 4; ++g) {
            int idx = g * UDIM + u;
            float v = b2[idx];
#pragma unroll
            for (int kc = 0; kc < KSPLIT; ++kc) v += __ldcg(&g_z2p[(size_t)(kc * BB + b) * N4 + idx]);
            z[g] = v;
        }
        float co = g_c2[b * UDIM + u];
        float cn = sigf(z[1]) * co + sigf(z[0]) * tanhf(z[2]);
        float hn = sigf(z[3]) * tanhf(cn);
        g_c2[b * UDIM + u] = cn;
        g_h2h[b * UDIM + u] = __float2half_rn(hn);
        xcat[u] = hn;
        xcat[UDIM + u] = __ldcg(&ctxr[b * UDIM + u]);
    }
    __syncthreads();
    int lane = tid & 31, w = tid >> 5;
    for (int v = w; v < VV; v += 8) {
        float p = 0.f;
        const float* wr = g_WdT + v * KDIM;
        for (int k = lane; k < KDIM; k += 32) p += xcat[k] * wr[k];
#pragma unroll
        for (int off = 16; off; off >>= 1) p += __shfl_xor_sync(0xffffffffu, p, off);
        if (lane == 0) lg[v] = p + bd[v];
    }
    __syncthreads();
    if (tid == 0) {
        float mx = lg[0];
        for (int v = 1; v < VV; ++v) mx = fmaxf(mx, lg[v]);
        float s = 0.f;
        for (int v = 0; v < VV; ++v) { float e = __expf(lg[v] - mx); lg[v] = e; s += e; }
        float inv = 1.f / s;
        for (int v = 0; v < VV; ++v) lg[v] *= inv;
    }
    __syncthreads();
    if (tid < VV) out[((size_t)b * TT + tprev) * VV + tid] = lg[tid];
    __syncthreads();
}

// ---------------- attention: LSTM1 gates + 3-slice online-softmax + last-block combine ----
__device__ __forceinline__ void attn_task(char* sm, const float* __restrict__ yv,
                                          const float* __restrict__ b1, int t, int bid) {
    int b = bid & 63;
    int p = bid >> 6;
    int tid = threadIdx.x;
    int lane = tid & 31, w = tid >> 5;
    float* h1s = (float*)sm;
    float (*reds)[UDIM] = (float(*)[UDIM])(sm + 2048);
    float* mwarp = (float*)(sm + 2048 + 16384);
    float* swarp = mwarp + 8;
    int* is_last_p = (int*)(swarp + 8);

    int par = t & 1;
    const float* c1r = g_c1 + par * BB * UDIM;
    float* c1w = g_c1 + (1 - par) * BB * UDIM;
    float* ctxw = g_ctx + (size_t)par * BB * UDIM;

    float yb = yv[b * TT + t];
#pragma unroll
    for (int r = 0; r < 2; ++r) {
        int u = tid + r * 256;
        float z[4];
#pragma unroll
        for (int g = 0; g < 4; ++g) {
            int idx = g * UDIM + u;
            float vvv = b1[idx] + yb * g_r1[idx];
#pragma unroll
            for (int kc = 0; kc < KSPLIT; ++kc) vvv += __ldcg(&g_z1p[(size_t)(kc * BB + b) * N4 + idx]);
            z[g] = vvv;
        }
        float co = __ldcg(&c1r[b * UDIM + u]);
        float cn = sigf(z[1]) * co + sigf(z[0]) * tanhf(z[2]);
        float hn = sigf(z[3]) * tanhf(cn);
        if (p == 0) {
            c1w[b * UDIM + u] = cn;
            g_h1h[b * UDIM + u] = __float2half_rn(hn);
        }
        h1s[u] = hn;
    }
    __syncthreads();

    float hr[16];
#pragma unroll
    for (int i = 0; i < 4; ++i) *(float4*)&hr[i * 4] = *(const float4*)&h1s[lane * 16 + i * 4];

    float acc[16];
#pragma unroll
    for (int j = 0; j < 16; ++j) acc[j] = 0.f;
    float m = -1e30f, sw = 0.f;
    const __half* hb = g_hh + (size_t)b * ET * UDIM;

    int tile0 = p * 11;
    int ntile = (p < 2) ? 11 : 10;
    for (int tile = 0; tile < ntile; ++tile) {
        int f0 = (tile0 + tile) * 32 + w * 4;
        float v[4][16];
        float sc[4];
#pragma unroll
        for (int fi = 0; fi < 4; ++fi) {
            const __half* hf = hb + (size_t)(f0 + fi) * UDIM + lane * 16;
            uint4 p0 = *(const uint4*)hf;
            uint4 p1 = *(const uint4*)(hf + 8);
            const unsigned pk[8] = {p0.x, p0.y, p0.z, p0.w, p1.x, p1.y, p1.z, p1.w};
#pragma unroll
            for (int q = 0; q < 8; ++q) {
                float2 f2 = __half22float2(*(const __half2*)&pk[q]);
                v[fi][q * 2] = f2.x;
                v[fi][q * 2 + 1] = f2.y;
            }
            float s = 0.f;
#pragma unroll
            for (int j = 0; j < 16; ++j) s += hr[j] * v[fi][j];
#pragma unroll
            for (int off = 16; off; off >>= 1) s += __shfl_xor_sync(0xffffffffu, s, off);
            sc[fi] = s;
        }
        float tv = fmaxf(fmaxf(sc[0], sc[1]), fmaxf(sc[2], sc[3]));
        float mn = fmaxf(m, tv);
        float scale = __expf(m - mn);
        m = mn;
        float p0 = __expf(sc[0] - mn), p1 = __expf(sc[1] - mn);
        float p2 = __expf(sc[2] - mn), p3 = __expf(sc[3] - mn);
        sw = sw * scale + (p0 + p1 + p2 + p3);
#pragma unroll
        for (int j = 0; j < 16; ++j)
            acc[j] = acc[j] * scale + p0 * v[0][j] + p1 * v[1][j] + p2 * v[2][j] + p3 * v[3][j];
    }

#pragma unroll
    for (int i = 0; i < 4; ++i) *(float4*)&reds[w][lane * 16 + i * 4] = *(float4*)&acc[i * 4];
    if (lane == 0) { mwarp[w] = m; swarp[w] = sw; }
    __syncthreads();

    float gm = mwarp[0];
#pragma unroll
    for (int ww = 1; ww < 8; ++ww) gm = fmaxf(gm, mwarp[ww]);
    float wsc[8];
    float sb = 0.f;
#pragma unroll
    for (int ww = 0; ww < 8; ++ww) { wsc[ww] = __expf(mwarp[ww] - gm); sb += swarp[ww] * wsc[ww]; }
    float* accp = g_accp + (size_t)(b * 4 + p) * UDIM;
#pragma unroll
    for (int r = 0; r < 2; ++r) {
        int d = tid + r * 256;
        float a = 0.f;
#pragma unroll
        for (int ww = 0; ww < 8; ++ww) a += reds[ww][d] * wsc[ww];
        accp[d] = a;
    }
    if (tid == 0) { g_mp[b * 4 + p] = gm; g_sp[b * 4 + p] = sb; }
    __threadfence();
    __syncthreads();
    if (tid == 0) {
        int old = atomicAdd(&g_cnt[b], 1);
        *is_last_p = (old == 2);
    }
    __syncthreads();
    if (*is_last_p) {
        if (tid == 0) g_cnt[b] = 0;
        float mp3[3], sp3[3];
#pragma unroll
        for (int q = 0; q < 3; ++q) { mp3[q] = __ldcg(&g_mp[b * 4 + q]); sp3[q] = __ldcg(&g_sp[b * 4 + q]); }
        float gm3 = fmaxf(fmaxf(mp3[0], mp3[1]), mp3[2]);
        float wsc3[3];
        float stot = 0.f;
#pragma unroll
        for (int q = 0; q < 3; ++q) { wsc3[q] = __expf(mp3[q] - gm3); stot += sp3[q] * wsc3[q]; }
        float inv = 1.f / stot;
#pragma unroll
        for (int r = 0; r < 2; ++r) {
            int d = tid + r * 256;
            float a = 0.f;
#pragma unroll
            for (int q = 0; q < 3; ++q) a += __ldcg(&g_accp[(size_t)(b * 4 + q) * UDIM + d]) * wsc3[q];
            float cv = a * inv;
            ctxw[b * UDIM + d] = cv;
            g_ctxh[b * UDIM + d] = __float2half_rn(cv);
        }
    }
    __syncthreads();
}

// ---------------- single persistent kernel: 2 phases per step ----------------
__global__ void __launch_bounds__(256, 2) fused_kernel(const float* __restrict__ yv,
                                                       const float* __restrict__ b1,
                                                       const float* __restrict__ b2,
                                                       const float* __restrict__ bd,
                                                       float* __restrict__ out) {
    extern __shared__ __align__(1024) char sm[];
    int bid = blockIdx.x;
    int ep = 0;
    // init phase: z1 GEMM for t=0 (h1,ctx are zero)
    if (bid >= 128) gemm_body(bid - 128, g_h1h, g_ctxh, g_M1t, g_z1p, sm);
    gbar(++ep * NBLK);
    for (int t = 0; t < TT; ++t) {
        // Phase X: attention(t) on blocks 0..191 || dec(t-1) on blocks 192..255
        if (bid < 192) attn_task(sm, yv, b1, t, bid);
        else if (t > 0) dec_body(sm, bid - 192, t - 1, (t - 1) & 1, b2, bd, out);
        gbar(++ep * NBLK);
        // Phase Y: z2 GEMM(t) on 0..127 || z1 GEMM(t+1) on 128..255
        if (bid < 128) gemm_body(bid, g_ctxh, g_h2h, g_M2t, g_z2p, sm);
        else if (t + 1 < TT) gemm_body(bid - 128, g_h1h, g_ctxh, g_M1t, g_z1p, sm);
        gbar(++ep * NBLK);
    }
    // epilogue: final LSTM2/logits
    if (bid >= 192) dec_body(sm, bid - 192, TT - 1, (TT - 1) & 1, b2, bd, out);
}

// ---------------- launcher (graph-capturable: kernel launches only) ----------------
extern "C" void kernel_launch(void* const* d_in, const int* in_sizes, int n_in,
                              void* d_out, int out_size) {
    (void)in_sizes; (void)n_in; (void)out_size;
    const float* h  = (const float*)d_in[0];
    const float* y  = (const float*)d_in[1];
    const float* W1 = (const float*)d_in[2];
    const float* U1 = (const float*)d_in[3];
    const float* b1 = (const float*)d_in[4];
    const float* W2 = (const float*)d_in[5];
    const float* U2 = (const float*)d_in[6];
    const float* b2 = (const float*)d_in[7];
    const float* Wd = (const float*)d_in[8];
    const float* bd = (const float*)d_in[9];
    float* out = (float*)d_out;

    cudaFuncSetAttribute(fused_kernel, cudaFuncAttributeMaxDynamicSharedMemorySize, SMBYTES_DYN);
    prologue_kernel<<<1024, 256>>>(W1, U1, W2, U2, Wd, h);
    fused_kernel<<<NBLK, 256, SMBYTES_DYN>>>(y, b1, b2, bd, out);
}